// round 7
// baseline (speedup 1.0000x reference)
#include <cuda_runtime.h>
#include <cuda_fp16.h>
#include <cstdint>
#include <cstring>

#define NN 100000
#define NE 1600000
#define LB 1563          // lin0 blocks in fused prep: ceil(100000/64)
#define EBF 6250         // edgefeat blocks: 1600000/256

// ---------------- device scratch (no allocation APIs allowed) ----------------
__device__ __align__(16) float g_X[NN * 64];     // node features fp32 (post-relu)
__device__ __align__(16) uint2 g_Dpk[NN * 32];   // dst proj packed fp16 (bias folded)
__device__ __align__(16) uint2 g_Spk[NN * 32];   // src proj packed fp16
__device__ __align__(16) unsigned g_E32[NE * 8]; // edge feats: 5 duplicated half2 + pad (32B)
__device__ __align__(16) int2 g_se[NE];          // per permuted slot: {src id, edge id}
__device__ int g_deg[NN];                        // statically zero; hist fills, scatter drains
__device__ int g_off[NN + 1];                    // CSR offsets (by dst)

__device__ __forceinline__ __half2 u2h(unsigned u) {
    __half2 h;
    memcpy(&h, &u, 4);
    return h;
}
__device__ __forceinline__ unsigned h2u(__half2 h) {
    unsigned u;
    memcpy(&u, &h, 4);
    return u;
}
__device__ __forceinline__ __half2 tanh_h2(__half2 x) {
    unsigned r, xu = h2u(x);
    asm("tanh.approx.f16x2 %0, %1;" : "=r"(r) : "r"(xu));
    return u2h(r);
}
__device__ __forceinline__ float softplus_f(float x) {
    return fmaxf(x, 0.0f) + __logf(1.0f + __expf(-fabsf(x)));
}

// ---------------------------------------------------------------------------
// CSR build (g_deg zero at start of each call: static init once, drained by
// scatter every call -> replay-invariant)
// ---------------------------------------------------------------------------
__global__ void k_hist(const int* __restrict__ ei) {
    int e = blockIdx.x * 256 + threadIdx.x;
    if (e < NE) atomicAdd(&g_deg[ei[NE + e]], 1);
}

__global__ __launch_bounds__(1024) void k_scan() {
    const int C = 98;
    int t = threadIdx.x;
    int beg = t * C;
    int end = min(beg + C, NN);
    int sum = 0;
    for (int i = beg; i < end; i++) sum += g_deg[i];

    __shared__ int wsum[32];
    int lane = t & 31, wid = t >> 5;
    int v = sum;
#pragma unroll
    for (int o = 1; o < 32; o <<= 1) {
        int u = __shfl_up_sync(0xffffffffu, v, o);
        if (lane >= o) v += u;
    }
    if (lane == 31) wsum[wid] = v;
    __syncthreads();
    if (wid == 0) {
        int w = wsum[lane];
#pragma unroll
        for (int o = 1; o < 32; o <<= 1) {
            int u = __shfl_up_sync(0xffffffffu, w, o);
            if (lane >= o) w += u;
        }
        wsum[lane] = w;
    }
    __syncthreads();
    int excl = v - sum + (wid > 0 ? wsum[wid - 1] : 0);
    int run = excl;
    for (int i = beg; i < end; i++) {
        g_off[i] = run;
        run += g_deg[i];
    }
    if (t == 1023) g_off[NN] = run;
}

__global__ void k_scatter(const int* __restrict__ ei) {
    int e = blockIdx.x * 256 + threadIdx.x;
    if (e >= NE) return;
    int d = ei[NE + e];
    int old = atomicSub(&g_deg[d], 1);   // drains deg back to 0 for next call
    int pos = g_off[d] + old - 1;
    g_se[pos] = make_int2(ei[e], e);     // one 8B store: {src, edge id}
}

// ---------------------------------------------------------------------------
// K_prep (fused): blocks [0,LB) -> X = relu(h@lin0_w+b);
// blocks [LB,LB+EBF): slot-ordered GATHER edgefeat -> coalesced 32B stores.
// ---------------------------------------------------------------------------
__global__ __launch_bounds__(256) void k_prep(const float* __restrict__ h,
                                              const float* __restrict__ w,
                                              const float* __restrict__ b,
                                              const float* __restrict__ ea,
                                              const float* __restrict__ sw,
                                              const float* __restrict__ sb) {
    const int t = threadIdx.x;
    if (blockIdx.x < LB) {
        __shared__ float Ws[64 * 64];
        __shared__ float Bs[64];
        __shared__ float Xs[8][64];
        for (int i = t; i < 64 * 64; i += 256) Ws[i] = w[i];
        if (t < 64) Bs[t] = b[t];

        const int base = blockIdx.x * 64;
        const int c = t & 63;
        const int r0 = t >> 6;

        for (int j = 0; j < 64; j += 8) {
            __syncthreads();
            for (int i = t; i < 8 * 64; i += 256) {
                int n = base + j + (i >> 6);
                Xs[i >> 6][i & 63] = (n < NN) ? h[(size_t)n * 64 + (i & 63)] : 0.0f;
            }
            __syncthreads();
#pragma unroll
            for (int rr = 0; rr < 2; rr++) {
                int row = r0 + rr * 4;
                int n = base + j + row;
                if (n < NN) {
                    float acc = Bs[c];
#pragma unroll
                    for (int k = 0; k < 64; k++)
                        acc = fmaf(Xs[row][k], Ws[k * 64 + c], acc);
                    g_X[(size_t)n * 64 + c] = fmaxf(acc, 0.0f);
                }
            }
        }
    } else {
        int p = (blockIdx.x - LB) * 256 + t;   // permuted slot (coalesced)
        if (p >= NE) return;
        int e = g_se[p].y;                     // coalesced 8B read
        const float* ap = ea + (size_t)e * 5;  // random 20B gather
        float a0 = ap[0], a1 = ap[1], a2 = ap[2], a3 = ap[3], a4 = ap[4];
        unsigned r[5];
#pragma unroll
        for (int c = 0; c < 5; c++) {
            float acc = sb[c];
            acc = fmaf(a0, sw[0 * 5 + c], acc);
            acc = fmaf(a1, sw[1 * 5 + c], acc);
            acc = fmaf(a2, sw[2 * 5 + c], acc);
            acc = fmaf(a3, sw[3 * 5 + c], acc);
            acc = fmaf(a4, sw[4 * 5 + c], acc);
            r[c] = h2u(__float2half2_rn(fmaxf(acc, 0.0f)));  // duplicated half2
        }
        uint4* o0 = reinterpret_cast<uint4*>(&g_E32[(size_t)p * 8]);
        o0[0] = make_uint4(r[0], r[1], r[2], r[3]);          // coalesced 16B
        o0[1] = make_uint4(r[4], 0u, 0u, 0u);                // coalesced 16B (pad)
    }
}

// ---------------------------------------------------------------------------
// K_proj: H=0 -> packed fp16 D (bias folded); H=1 -> packed fp16 S.
// 128x128 tile, 8x8 per thread.
// ---------------------------------------------------------------------------
__global__ __launch_bounds__(256) void k_proj(const float* __restrict__ wf,
                                              const float* __restrict__ ws,
                                              const float* __restrict__ bf,
                                              const float* __restrict__ bs) {
    __shared__ float Xs[32 * 129];
    __shared__ float Wsm[32 * 128];
    const int t = threadIdx.x;
    const int tx = t & 15, ty = t >> 4;
    const int H = blockIdx.y;
    const int base = blockIdx.x * 128;

    float acc[8][8];
#pragma unroll
    for (int i = 0; i < 8; i++)
#pragma unroll
        for (int j = 0; j < 8; j++) acc[i][j] = 0.0f;

    for (int ks = 0; ks < 64; ks += 32) {
        __syncthreads();
#pragma unroll
        for (int r = 0; r < 16; r++) {
            int idx = t + 256 * r;
            int n = idx >> 5;
            int k = idx & 31;
            int gn = base + n;
            Xs[k * 129 + n] = (gn < NN) ? g_X[(size_t)gn * 64 + ks + k] : 0.0f;
        }
#pragma unroll
        for (int r = 0; r < 16; r++) {
            int idx = t + 256 * r;
            int k = idx >> 7;
            int c = idx & 127;
            int grow = H * 64 + ks + k;
            Wsm[k * 128 + c] = (c < 64) ? wf[grow * 64 + c] : ws[grow * 64 + (c - 64)];
        }
        __syncthreads();
#pragma unroll
        for (int k = 0; k < 32; k++) {
            float xr[8], wr[8];
#pragma unroll
            for (int i = 0; i < 8; i++) xr[i] = Xs[k * 129 + i * 16 + ty];
#pragma unroll
            for (int j = 0; j < 8; j++) wr[j] = Wsm[k * 128 + j * 16 + tx];
#pragma unroll
            for (int i = 0; i < 8; i++)
#pragma unroll
                for (int j = 0; j < 8; j++)
                    acc[i][j] = fmaf(xr[i], wr[j], acc[i][j]);
        }
    }

    __half* outp = reinterpret_cast<__half*>(H == 0 ? g_Dpk : g_Spk);
#pragma unroll
    for (int i = 0; i < 8; i++) {
        int n = base + i * 16 + ty;
        if (n >= NN) continue;
#pragma unroll
        for (int j = 0; j < 8; j++) {
            int c = j * 16 + tx;
            float v = acc[i][j];
            if (H == 0) v += (c < 64) ? bf[c] : bs[c - 64];
            int cc = (c < 64) ? c : c - 64;
            int posh = 4 * (cc >> 1) + ((c < 64) ? 0 : 2) + (cc & 1);
            outp[(size_t)n * 128 + posh] = __float2half(v);
        }
    }
}

// ---------------------------------------------------------------------------
// K_edge_csr: one WARP per dst node; lane l owns channels 2l,2l+1 as half2.
// Depth-2 software pipeline: at iter k, issue Spk for k+1 (src known since
// k-1) and src for k+2; compute with Spk of k. Fused residual+relu epilogue.
// ---------------------------------------------------------------------------
__global__ __launch_bounds__(256) void k_edge_csr(const float* __restrict__ wef,
                                                  const float* __restrict__ wes,
                                                  float* __restrict__ out,
                                                  int final_) {
    int gw = (blockIdx.x * 256 + threadIdx.x) >> 5;
    int l = threadIdx.x & 31;
    if (gw >= NN) return;
    const int n = gw;

    __half2 wf2[5], ws2[5];
#pragma unroll
    for (int k = 0; k < 5; k++) {
        wf2[k] = __floats2half2_rn(wef[k * 64 + 2 * l], wef[k * 64 + 2 * l + 1]);
        ws2[k] = __floats2half2_rn(wes[k * 64 + 2 * l], wes[k * 64 + 2 * l + 1]);
    }
    const __half2 cHalf = __float2half2_rn(0.5f);

    uint2 dw = g_Dpk[(size_t)n * 32 + l];
    const __half2 Df2 = u2h(dw.x);
    const __half2 Ds2 = u2h(dw.y);

    float m0 = 0.0f, m1 = 0.0f;
    const int beg = __ldg(&g_off[n]), end = __ldg(&g_off[n + 1]);

    if (beg < end) {
        int sA = __ldg(&g_se[beg]).x;                       // src of edge beg
        int sB = (beg + 1 < end) ? __ldg(&g_se[beg + 1]).x : sA;
        uint2 spCur = __ldg(&g_Spk[(size_t)sA * 32 + l]);

#pragma unroll 2
        for (int k = beg; k < end; k++) {
            // prefetch: Spk for k+1 (sB known), src for k+2
            uint2 spNext = __ldg(&g_Spk[(size_t)sB * 32 + l]);
            int kc = (k + 2 < end) ? k + 2 : end - 1;
            int sC = __ldg(&g_se[kc]).x;

            uint4 ew = *reinterpret_cast<const uint4*>(&g_E32[(size_t)k * 8]);
            unsigned e4w = g_E32[(size_t)k * 8 + 4];

            __half2 zf = __hadd2(Df2, u2h(spCur.x));
            zf = __hfma2(u2h(ew.x), wf2[0], zf);
            zf = __hfma2(u2h(ew.y), wf2[1], zf);
            zf = __hfma2(u2h(ew.z), wf2[2], zf);
            zf = __hfma2(u2h(ew.w), wf2[3], zf);
            zf = __hfma2(u2h(e4w), wf2[4], zf);

            __half2 zs = __hadd2(Ds2, u2h(spCur.y));
            zs = __hfma2(u2h(ew.x), ws2[0], zs);
            zs = __hfma2(u2h(ew.y), ws2[1], zs);
            zs = __hfma2(u2h(ew.z), ws2[2], zs);
            zs = __hfma2(u2h(ew.w), ws2[3], zs);
            zs = __hfma2(u2h(e4w), ws2[4], zs);

            __half2 g2 = __hfma2(tanh_h2(__hmul2(zf, cHalf)), cHalf, cHalf);
            float2 gf = __half22float2(g2);
            float2 zsf = __half22float2(zs);

            m0 = fmaf(gf.x, softplus_f(zsf.x), m0);
            m1 = fmaf(gf.y, softplus_f(zsf.y), m1);

            spCur = spNext;
            sB = sC;
        }
    }

    float2 x = *reinterpret_cast<const float2*>(g_X + (size_t)n * 64 + 2 * l);
    float2 r = make_float2(fmaxf(x.x + m0, 0.0f), fmaxf(x.y + m1, 0.0f));
    if (final_) {
        *reinterpret_cast<float2*>(out + (size_t)n * 64 + 2 * l) = r;
    } else {
        *reinterpret_cast<float2*>(g_X + (size_t)n * 64 + 2 * l) = r;
    }
}

// ---------------------------------------------------------------------------
// Launch. Inputs: h, edge_index, edge_weight, edge_attr, data,
// lin0_w, lin0_b, short_w, short_b, conv_f_w, conv_f_b, conv_s_w, conv_s_b
// First k_edge_csr is launch #6 (ncu -s 5 -c 1 target).
// ---------------------------------------------------------------------------
extern "C" void kernel_launch(void* const* d_in, const int* in_sizes, int n_in,
                              void* d_out, int out_size) {
    int o = (n_in >= 13) ? 0 : -1;

    const float* h = (const float*)d_in[0];
    const int* ei = (const int*)d_in[1];  // int32 [2, NE]
    const float* ea = (const float*)d_in[3];
    const float* lin0_w = (const float*)d_in[5 + o];
    const float* lin0_b = (const float*)d_in[6 + o];
    const float* short_w = (const float*)d_in[7 + o];
    const float* short_b = (const float*)d_in[8 + o];
    const float* cfw = (const float*)d_in[9 + o];   // [2,133,64]
    const float* cfb = (const float*)d_in[10 + o];  // [2,64]
    const float* csw = (const float*)d_in[11 + o];
    const float* csb = (const float*)d_in[12 + o];
    float* out = (float*)d_out;

    const int EB = (NE + 255) / 256;

    k_hist<<<EB, 256>>>(ei);        // 1
    k_scan<<<1, 1024>>>();          // 2
    k_scatter<<<EB, 256>>>(ei);     // 3
    k_prep<<<LB + EBF, 256>>>(h, lin0_w, lin0_b, ea, short_w, short_b);  // 4

    for (int i = 0; i < 2; i++) {
        const float* wf = cfw + (size_t)i * 133 * 64;
        const float* ws = csw + (size_t)i * 133 * 64;
        dim3 pg((NN + 127) / 128, 2);
        k_proj<<<pg, 256>>>(wf, ws, cfb + i * 64, csb + i * 64);         // 5 / 7
        k_edge_csr<<<(NN * 32 + 255) / 256, 256>>>(wf + 128 * 64, ws + 128 * 64,
                                                   out, i == 1 ? 1 : 0); // 6 / 8
    }
}

// round 9
// speedup vs baseline: 1.1302x; 1.1302x over previous
#include <cuda_runtime.h>
#include <cuda_fp16.h>
#include <cstdint>
#include <cstring>

#define NN 100000
#define NE 1600000

// ---------------- device scratch (no allocation APIs allowed) ----------------
__device__ __align__(16) float g_X[NN * 64];     // node features fp32 (post-relu)
__device__ __align__(16) uint2 g_Dpk[NN * 32];   // dst proj packed fp16 (bias folded)
__device__ __align__(16) uint2 g_Spk[NN * 32];   // src proj packed fp16
__device__ __align__(16) unsigned g_E32[NE * 8]; // edge feats: 5 duplicated half2 + pad (32B)
__device__ int g_srcp[NE];                       // src id, permuted (sorted by dst)
__device__ int g_deg[NN];                        // statically zero; hist fills, scatter drains
__device__ int g_off[NN + 1];                    // CSR offsets (by dst)

__device__ __forceinline__ __half2 u2h(unsigned u) {
    __half2 h;
    memcpy(&h, &u, 4);
    return h;
}
__device__ __forceinline__ unsigned h2u(__half2 h) {
    unsigned u;
    memcpy(&u, &h, 4);
    return u;
}
__device__ __forceinline__ __half2 tanh_h2(__half2 x) {
    unsigned r, xu = h2u(x);
    asm("tanh.approx.f16x2 %0, %1;" : "=r"(r) : "r"(xu));
    return u2h(r);
}
__device__ __forceinline__ float softplus_f(float x) {
    return fmaxf(x, 0.0f) + __logf(1.0f + __expf(-fabsf(x)));
}

// ---------------------------------------------------------------------------
// CSR build. g_deg is zero at entry every call (static init once; scatter
// drains it back to zero) -> graph-replay invariant.
// ---------------------------------------------------------------------------
__global__ void k_hist(const int* __restrict__ ei) {
    int e = blockIdx.x * 256 + threadIdx.x;
    if (e < NE) atomicAdd(&g_deg[ei[NE + e]], 1);
}

__global__ __launch_bounds__(1024) void k_scan() {
    const int C = 98;
    int t = threadIdx.x;
    int beg = t * C;
    int end = min(beg + C, NN);
    int sum = 0;
    for (int i = beg; i < end; i++) sum += g_deg[i];

    __shared__ int wsum[32];
    int lane = t & 31, wid = t >> 5;
    int v = sum;
#pragma unroll
    for (int o = 1; o < 32; o <<= 1) {
        int u = __shfl_up_sync(0xffffffffu, v, o);
        if (lane >= o) v += u;
    }
    if (lane == 31) wsum[wid] = v;
    __syncthreads();
    if (wid == 0) {
        int w = wsum[lane];
#pragma unroll
        for (int o = 1; o < 32; o <<= 1) {
            int u = __shfl_up_sync(0xffffffffu, w, o);
            if (lane >= o) w += u;
        }
        wsum[lane] = w;
    }
    __syncthreads();
    int excl = v - sum + (wid > 0 ? wsum[wid - 1] : 0);
    int run = excl;
    for (int i = beg; i < end; i++) {
        g_off[i] = run;
        run += g_deg[i];
    }
    if (t == 1023) g_off[NN] = run;
}

// ---------------------------------------------------------------------------
// k_scatter_feat: for edge e (original order, coalesced ea read), compute slot,
// store src id (4B scattered) AND the 5 relu'd edge features as duplicated
// half2 (2 x 16B sector-aligned scattered stores, full-sector writes).
// Drains g_deg back to 0.
// ---------------------------------------------------------------------------
__global__ __launch_bounds__(256) void k_scatter_feat(const int* __restrict__ ei,
                                                      const float* __restrict__ ea,
                                                      const float* __restrict__ sw,
                                                      const float* __restrict__ sb) {
    int e = blockIdx.x * 256 + threadIdx.x;
    if (e >= NE) return;
    int d = ei[NE + e];
    int old = atomicSub(&g_deg[d], 1);
    int pos = g_off[d] + old - 1;
    g_srcp[pos] = ei[e];

    const float* ap = ea + (size_t)e * 5;   // coalesced across warp
    float a0 = ap[0], a1 = ap[1], a2 = ap[2], a3 = ap[3], a4 = ap[4];
    unsigned r[5];
#pragma unroll
    for (int c = 0; c < 5; c++) {
        float acc = sb[c];
        acc = fmaf(a0, sw[0 * 5 + c], acc);
        acc = fmaf(a1, sw[1 * 5 + c], acc);
        acc = fmaf(a2, sw[2 * 5 + c], acc);
        acc = fmaf(a3, sw[3 * 5 + c], acc);
        acc = fmaf(a4, sw[4 * 5 + c], acc);
        r[c] = h2u(__float2half2_rn(fmaxf(acc, 0.0f)));  // duplicated half2
    }
    uint4* o0 = reinterpret_cast<uint4*>(&g_E32[(size_t)pos * 8]);
    o0[0] = make_uint4(r[0], r[1], r[2], r[3]);
    o0[1] = make_uint4(r[4], 0u, 0u, 0u);
}

// ---------------------------------------------------------------------------
// k_lin0: X = relu(h @ lin0_w + b). 64 nodes x 64 cols per 256-thread block
// (16x16), 4 rows x 4 cols per thread. Xs [k][node] stride 65 (16.6KB) +
// Wsm [k][col] (16KB) = 32.6KB static smem.
// ---------------------------------------------------------------------------
__global__ __launch_bounds__(256) void k_lin0(const float* __restrict__ h,
                                              const float* __restrict__ w,
                                              const float* __restrict__ b) {
    __shared__ float Xs[64 * 65];
    __shared__ float Wsm[64 * 64];
    const int t = threadIdx.x;
    const int tx = t & 15, ty = t >> 4;
    const int base = blockIdx.x * 64;

    float acc[4][4];
#pragma unroll
    for (int i = 0; i < 4; i++)
#pragma unroll
        for (int j = 0; j < 4; j++) acc[i][j] = 0.0f;

#pragma unroll
    for (int r = 0; r < 16; r++) {
        int idx = t + 256 * r;   // 0..4095
        int n = idx >> 6;        // 0..63
        int k = idx & 63;
        int gn = base + n;
        Xs[k * 65 + n] = (gn < NN) ? h[(size_t)gn * 64 + k] : 0.0f;
    }
#pragma unroll
    for (int r = 0; r < 16; r++) {
        int idx = t + 256 * r;
        Wsm[idx] = w[idx];       // [k][col] row-major already
    }
    __syncthreads();

#pragma unroll
    for (int k = 0; k < 64; k++) {
        float xr[4], wr[4];
#pragma unroll
        for (int i = 0; i < 4; i++) xr[i] = Xs[k * 65 + i * 16 + ty];
#pragma unroll
        for (int j = 0; j < 4; j++) wr[j] = Wsm[k * 64 + j * 16 + tx];
#pragma unroll
        for (int i = 0; i < 4; i++)
#pragma unroll
            for (int j = 0; j < 4; j++)
                acc[i][j] = fmaf(xr[i], wr[j], acc[i][j]);
    }

#pragma unroll
    for (int i = 0; i < 4; i++) {
        int n = base + i * 16 + ty;
        if (n >= NN) continue;
#pragma unroll
        for (int j = 0; j < 4; j++) {
            int c = j * 16 + tx;
            g_X[(size_t)n * 64 + c] = fmaxf(acc[i][j] + b[c], 0.0f);
        }
    }
}

// ---------------------------------------------------------------------------
// K_proj: H=0 -> packed fp16 D (bias folded); H=1 -> packed fp16 S.
// 128x128 tile, 8x8 per thread.
// ---------------------------------------------------------------------------
__global__ __launch_bounds__(256) void k_proj(const float* __restrict__ wf,
                                              const float* __restrict__ ws,
                                              const float* __restrict__ bf,
                                              const float* __restrict__ bs) {
    __shared__ float Xs[32 * 129];
    __shared__ float Wsm[32 * 128];
    const int t = threadIdx.x;
    const int tx = t & 15, ty = t >> 4;
    const int H = blockIdx.y;
    const int base = blockIdx.x * 128;

    float acc[8][8];
#pragma unroll
    for (int i = 0; i < 8; i++)
#pragma unroll
        for (int j = 0; j < 8; j++) acc[i][j] = 0.0f;

    for (int ks = 0; ks < 64; ks += 32) {
        __syncthreads();
#pragma unroll
        for (int r = 0; r < 16; r++) {
            int idx = t + 256 * r;
            int n = idx >> 5;
            int k = idx & 31;
            int gn = base + n;
            Xs[k * 129 + n] = (gn < NN) ? g_X[(size_t)gn * 64 + ks + k] : 0.0f;
        }
#pragma unroll
        for (int r = 0; r < 16; r++) {
            int idx = t + 256 * r;
            int k = idx >> 7;
            int c = idx & 127;
            int grow = H * 64 + ks + k;
            Wsm[k * 128 + c] = (c < 64) ? wf[grow * 64 + c] : ws[grow * 64 + (c - 64)];
        }
        __syncthreads();
#pragma unroll
        for (int k = 0; k < 32; k++) {
            float xr[8], wr[8];
#pragma unroll
            for (int i = 0; i < 8; i++) xr[i] = Xs[k * 129 + i * 16 + ty];
#pragma unroll
            for (int j = 0; j < 8; j++) wr[j] = Wsm[k * 128 + j * 16 + tx];
#pragma unroll
            for (int i = 0; i < 8; i++)
#pragma unroll
                for (int j = 0; j < 8; j++)
                    acc[i][j] = fmaf(xr[i], wr[j], acc[i][j]);
        }
    }

    __half* outp = reinterpret_cast<__half*>(H == 0 ? g_Dpk : g_Spk);
#pragma unroll
    for (int i = 0; i < 8; i++) {
        int n = base + i * 16 + ty;
        if (n >= NN) continue;
#pragma unroll
        for (int j = 0; j < 8; j++) {
            int c = j * 16 + tx;
            float v = acc[i][j];
            if (H == 0) v += (c < 64) ? bf[c] : bs[c - 64];
            int cc = (c < 64) ? c : c - 64;
            int posh = 4 * (cc >> 1) + ((c < 64) ? 0 : 2) + (cc & 1);
            outp[(size_t)n * 128 + posh] = __float2half(v);
        }
    }
}

// ---------------------------------------------------------------------------
// K_edge_csr: one WARP per dst node; lane l owns channels 2l,2l+1 as half2.
// Simple loop, unroll 4 (compiler batches independent srcp->Spk chains).
// Fused residual + relu epilogue.
// ---------------------------------------------------------------------------
__global__ __launch_bounds__(256) void k_edge_csr(const float* __restrict__ wef,
                                                  const float* __restrict__ wes,
                                                  float* __restrict__ out,
                                                  int final_) {
    int gw = (blockIdx.x * 256 + threadIdx.x) >> 5;
    int l = threadIdx.x & 31;
    if (gw >= NN) return;
    const int n = gw;

    __half2 wf2[5], ws2[5];
#pragma unroll
    for (int k = 0; k < 5; k++) {
        wf2[k] = __floats2half2_rn(wef[k * 64 + 2 * l], wef[k * 64 + 2 * l + 1]);
        ws2[k] = __floats2half2_rn(wes[k * 64 + 2 * l], wes[k * 64 + 2 * l + 1]);
    }
    const __half2 cHalf = __float2half2_rn(0.5f);

    uint2 dw = g_Dpk[(size_t)n * 32 + l];
    const __half2 Df2 = u2h(dw.x);
    const __half2 Ds2 = u2h(dw.y);

    float m0 = 0.0f, m1 = 0.0f;
    const int beg = __ldg(&g_off[n]), end = __ldg(&g_off[n + 1]);

#pragma unroll 4
    for (int k = beg; k < end; k++) {
        int s = __ldg(&g_srcp[k]);                            // 4B bcast
        uint4 ew = *reinterpret_cast<const uint4*>(&g_E32[(size_t)k * 8]);
        unsigned e4w = g_E32[(size_t)k * 8 + 4];
        uint2 sp_ = __ldg(&g_Spk[(size_t)s * 32 + l]);        // 8B gather

        __half2 zf = __hadd2(Df2, u2h(sp_.x));
        zf = __hfma2(u2h(ew.x), wf2[0], zf);
        zf = __hfma2(u2h(ew.y), wf2[1], zf);
        zf = __hfma2(u2h(ew.z), wf2[2], zf);
        zf = __hfma2(u2h(ew.w), wf2[3], zf);
        zf = __hfma2(u2h(e4w), wf2[4], zf);

        __half2 zs = __hadd2(Ds2, u2h(sp_.y));
        zs = __hfma2(u2h(ew.x), ws2[0], zs);
        zs = __hfma2(u2h(ew.y), ws2[1], zs);
        zs = __hfma2(u2h(ew.z), ws2[2], zs);
        zs = __hfma2(u2h(ew.w), ws2[3], zs);
        zs = __hfma2(u2h(e4w), ws2[4], zs);

        __half2 g2 = __hfma2(tanh_h2(__hmul2(zf, cHalf)), cHalf, cHalf);
        float2 gf = __half22float2(g2);
        float2 zsf = __half22float2(zs);

        m0 = fmaf(gf.x, softplus_f(zsf.x), m0);
        m1 = fmaf(gf.y, softplus_f(zsf.y), m1);
    }

    float2 x = *reinterpret_cast<const float2*>(g_X + (size_t)n * 64 + 2 * l);
    float2 r = make_float2(fmaxf(x.x + m0, 0.0f), fmaxf(x.y + m1, 0.0f));
    if (final_) {
        *reinterpret_cast<float2*>(out + (size_t)n * 64 + 2 * l) = r;
    } else {
        *reinterpret_cast<float2*>(g_X + (size_t)n * 64 + 2 * l) = r;
    }
}

// ---------------------------------------------------------------------------
// Launch. Inputs: h, edge_index, edge_weight, edge_attr, data,
// lin0_w, lin0_b, short_w, short_b, conv_f_w, conv_f_b, conv_s_w, conv_s_b
// First k_edge_csr is launch #6 (ncu -s 5 -c 1 target).
// ---------------------------------------------------------------------------
extern "C" void kernel_launch(void* const* d_in, const int* in_sizes, int n_in,
                              void* d_out, int out_size) {
    int o = (n_in >= 13) ? 0 : -1;

    const float* h = (const float*)d_in[0];
    const int* ei = (const int*)d_in[1];  // int32 [2, NE]
    const float* ea = (const float*)d_in[3];
    const float* lin0_w = (const float*)d_in[5 + o];
    const float* lin0_b = (const float*)d_in[6 + o];
    const float* short_w = (const float*)d_in[7 + o];
    const float* short_b = (const float*)d_in[8 + o];
    const float* cfw = (const float*)d_in[9 + o];   // [2,133,64]
    const float* cfb = (const float*)d_in[10 + o];  // [2,64]
    const float* csw = (const float*)d_in[11 + o];
    const float* csb = (const float*)d_in[12 + o];
    float* out = (float*)d_out;

    const int EB = (NE + 255) / 256;

    k_hist<<<EB, 256>>>(ei);                                       // 1
    k_scan<<<1, 1024>>>();                                         // 2
    k_scatter_feat<<<EB, 256>>>(ei, ea, short_w, short_b);         // 3
    k_lin0<<<(NN + 63) / 64, 256>>>(h, lin0_w, lin0_b);            // 4

    for (int i = 0; i < 2; i++) {
        const float* wf = cfw + (size_t)i * 133 * 64;
        const float* ws = csw + (size_t)i * 133 * 64;
        dim3 pg((NN + 127) / 128, 2);
        k_proj<<<pg, 256>>>(wf, ws, cfb + i * 64, csb + i * 64);   // 5 / 7
        k_edge_csr<<<(NN * 32 + 255) / 256, 256>>>(wf + 128 * 64, ws + 128 * 64,
                                                   out, i == 1);   // 6 / 8
    }
}

// round 11
// speedup vs baseline: 1.1369x; 1.0060x over previous
#include <cuda_runtime.h>
#include <cuda_fp16.h>
#include <cstdint>
#include <cstring>

#define NN 100000
#define NE 1600000
#define EB 6250            // edge blocks: 1600000/256
#define LB 1563            // lin0 blocks: ceil(100000/64)
#define PB 782             // proj blocks per half: ceil(100000/128)

// ---------------- device scratch (no allocation APIs allowed) ----------------
__device__ __align__(16) float g_X[NN * 64];     // node features fp32 (post-relu)
__device__ __align__(16) uint2 g_Dpk[NN * 32];   // dst proj packed fp16 (bias folded)
__device__ __align__(16) uint2 g_Spk[NN * 32];   // src proj packed fp16
__device__ __align__(16) unsigned g_E32[NE * 8]; // per slot: {e0,e1,e2,e3 | e4,src,0,0}
__device__ int g_deg[NN];                        // statically zero; hist fills, scatter drains
__device__ int g_off[NN + 1];                    // CSR offsets (by dst)

__device__ __forceinline__ __half2 u2h(unsigned u) {
    __half2 h;
    memcpy(&h, &u, 4);
    return h;
}
__device__ __forceinline__ unsigned h2u(__half2 h) {
    unsigned u;
    memcpy(&u, &h, 4);
    return u;
}
__device__ __forceinline__ __half2 tanh_h2(__half2 x) {
    unsigned r, xu = h2u(x);
    asm("tanh.approx.f16x2 %0, %1;" : "=r"(r) : "r"(xu));
    return u2h(r);
}
__device__ __forceinline__ float softplus_f(float x) {
    return fmaxf(x, 0.0f) + __logf(1.0f + __expf(-fabsf(x)));
}

// ---------------------------------------------------------------------------
// Launch 1 (fused): blocks [0,EB) -> degree histogram;
//                   blocks [EB,EB+LB) -> X = relu(h @ lin0_w + b) (64x64 GEMM).
// Independent work items run concurrently in one capture-safe launch.
// ---------------------------------------------------------------------------
__global__ __launch_bounds__(256) void k_hist_lin0(const int* __restrict__ ei,
                                                   const float* __restrict__ h,
                                                   const float* __restrict__ w,
                                                   const float* __restrict__ b) {
    __shared__ float Xs[64 * 65];
    __shared__ float Wsm[64 * 64];
    const int t = threadIdx.x;

    if (blockIdx.x < EB) {
        int e = blockIdx.x * 256 + t;
        if (e < NE) atomicAdd(&g_deg[ei[NE + e]], 1);
        return;
    }

    const int tx = t & 15, ty = t >> 4;
    const int base = (blockIdx.x - EB) * 64;

    float acc[4][4];
#pragma unroll
    for (int i = 0; i < 4; i++)
#pragma unroll
        for (int j = 0; j < 4; j++) acc[i][j] = 0.0f;

#pragma unroll
    for (int r = 0; r < 16; r++) {
        int idx = t + 256 * r;   // 0..4095
        int n = idx >> 6;
        int k = idx & 63;
        int gn = base + n;
        Xs[k * 65 + n] = (gn < NN) ? h[(size_t)gn * 64 + k] : 0.0f;
    }
#pragma unroll
    for (int r = 0; r < 16; r++) {
        int idx = t + 256 * r;
        Wsm[idx] = w[idx];
    }
    __syncthreads();

#pragma unroll
    for (int k = 0; k < 64; k++) {
        float xr[4], wr[4];
#pragma unroll
        for (int i = 0; i < 4; i++) xr[i] = Xs[k * 65 + i * 16 + ty];
#pragma unroll
        for (int j = 0; j < 4; j++) wr[j] = Wsm[k * 64 + j * 16 + tx];
#pragma unroll
        for (int i = 0; i < 4; i++)
#pragma unroll
            for (int j = 0; j < 4; j++)
                acc[i][j] = fmaf(xr[i], wr[j], acc[i][j]);
    }

#pragma unroll
    for (int i = 0; i < 4; i++) {
        int n = base + i * 16 + ty;
        if (n >= NN) continue;
#pragma unroll
        for (int j = 0; j < 4; j++) {
            int c = j * 16 + tx;
            g_X[(size_t)n * 64 + c] = fmaxf(acc[i][j] + b[c], 0.0f);
        }
    }
}

// ---------------------------------------------------------------------------
// Launch 2: exclusive scan of degrees -> g_off. (g_deg untouched here.)
// ---------------------------------------------------------------------------
__global__ __launch_bounds__(1024) void k_scan() {
    const int C = 98;
    int t = threadIdx.x;
    int beg = t * C;
    int end = min(beg + C, NN);
    int sum = 0;
    for (int i = beg; i < end; i++) sum += g_deg[i];

    __shared__ int wsum[32];
    int lane = t & 31, wid = t >> 5;
    int v = sum;
#pragma unroll
    for (int o = 1; o < 32; o <<= 1) {
        int u = __shfl_up_sync(0xffffffffu, v, o);
        if (lane >= o) v += u;
    }
    if (lane == 31) wsum[wid] = v;
    __syncthreads();
    if (wid == 0) {
        int w = wsum[lane];
#pragma unroll
        for (int o = 1; o < 32; o <<= 1) {
            int u = __shfl_up_sync(0xffffffffu, w, o);
            if (lane >= o) w += u;
        }
        wsum[lane] = w;
    }
    __syncthreads();
    int excl = v - sum + (wid > 0 ? wsum[wid - 1] : 0);
    int run = excl;
    for (int i = beg; i < end; i++) {
        g_off[i] = run;
        run += g_deg[i];
    }
    if (t == 1023) g_off[NN] = run;
}

// ---------------------------------------------------------------------------
// Proj body (device fn): 128x128 tile, 8x8/thread.
// H=0 -> packed fp16 D (bias folded); H=1 -> packed fp16 S.
// ---------------------------------------------------------------------------
__device__ __forceinline__ void proj_body(float* Xs, float* Wsm, int bidx,
                                          const float* __restrict__ wf,
                                          const float* __restrict__ ws,
                                          const float* __restrict__ bf,
                                          const float* __restrict__ bs) {
    const int t = threadIdx.x;
    const int tx = t & 15, ty = t >> 4;
    const int H = bidx / PB;           // 0 or 1
    const int base = (bidx % PB) * 128;

    float acc[8][8];
#pragma unroll
    for (int i = 0; i < 8; i++)
#pragma unroll
        for (int j = 0; j < 8; j++) acc[i][j] = 0.0f;

    for (int ks = 0; ks < 64; ks += 32) {
        __syncthreads();
#pragma unroll
        for (int r = 0; r < 16; r++) {
            int idx = t + 256 * r;
            int n = idx >> 5;
            int k = idx & 31;
            int gn = base + n;
            Xs[k * 129 + n] = (gn < NN) ? g_X[(size_t)gn * 64 + ks + k] : 0.0f;
        }
#pragma unroll
        for (int r = 0; r < 16; r++) {
            int idx = t + 256 * r;
            int k = idx >> 7;
            int c = idx & 127;
            int grow = H * 64 + ks + k;
            Wsm[k * 128 + c] = (c < 64) ? wf[grow * 64 + c] : ws[grow * 64 + (c - 64)];
        }
        __syncthreads();
#pragma unroll
        for (int k = 0; k < 32; k++) {
            float xr[8], wr[8];
#pragma unroll
            for (int i = 0; i < 8; i++) xr[i] = Xs[k * 129 + i * 16 + ty];
#pragma unroll
            for (int j = 0; j < 8; j++) wr[j] = Wsm[k * 128 + j * 16 + tx];
#pragma unroll
            for (int i = 0; i < 8; i++)
#pragma unroll
                for (int j = 0; j < 8; j++)
                    acc[i][j] = fmaf(xr[i], wr[j], acc[i][j]);
        }
    }

    __half* outp = reinterpret_cast<__half*>(H == 0 ? g_Dpk : g_Spk);
#pragma unroll
    for (int i = 0; i < 8; i++) {
        int n = base + i * 16 + ty;
        if (n >= NN) continue;
#pragma unroll
        for (int j = 0; j < 8; j++) {
            int c = j * 16 + tx;
            float v = acc[i][j];
            if (H == 0) v += (c < 64) ? bf[c] : bs[c - 64];
            int cc = (c < 64) ? c : c - 64;
            int posh = 4 * (cc >> 1) + ((c < 64) ? 0 : 2) + (cc & 1);
            outp[(size_t)n * 128 + posh] = __float2half(v);
        }
    }
}

// ---------------------------------------------------------------------------
// scatter_feat body: edge e -> slot pos; write {5 feats as dup half2, src id}
// as TWO 16B sector stores. Drains g_deg back to 0.
// ---------------------------------------------------------------------------
__device__ __forceinline__ void scatter_feat_body(int e,
                                                  const int* __restrict__ ei,
                                                  const float* __restrict__ ea,
                                                  const float* __restrict__ sw,
                                                  const float* __restrict__ sb) {
    if (e >= NE) return;
    int d = ei[NE + e];
    int old = atomicSub(&g_deg[d], 1);
    int pos = g_off[d] + old - 1;

    const float* ap = ea + (size_t)e * 5;
    float a0 = ap[0], a1 = ap[1], a2 = ap[2], a3 = ap[3], a4 = ap[4];
    unsigned r[5];
#pragma unroll
    for (int c = 0; c < 5; c++) {
        float acc = sb[c];
        acc = fmaf(a0, sw[0 * 5 + c], acc);
        acc = fmaf(a1, sw[1 * 5 + c], acc);
        acc = fmaf(a2, sw[2 * 5 + c], acc);
        acc = fmaf(a3, sw[3 * 5 + c], acc);
        acc = fmaf(a4, sw[4 * 5 + c], acc);
        r[c] = h2u(__float2half2_rn(fmaxf(acc, 0.0f)));
    }
    uint4* o0 = reinterpret_cast<uint4*>(&g_E32[(size_t)pos * 8]);
    o0[0] = make_uint4(r[0], r[1], r[2], r[3]);
    o0[1] = make_uint4(r[4], (unsigned)ei[e], 0u, 0u);
}

// ---------------------------------------------------------------------------
// Launch 3 (fused): blocks [0,2*PB) -> proj conv#1; blocks [2*PB,..) ->
// scatter_feat. Both dep-ready after launches 1-2; run concurrently.
// ---------------------------------------------------------------------------
__global__ __launch_bounds__(256) void k_scat_proj(const int* __restrict__ ei,
                                                   const float* __restrict__ ea,
                                                   const float* __restrict__ sw,
                                                   const float* __restrict__ sb,
                                                   const float* __restrict__ wf,
                                                   const float* __restrict__ ws,
                                                   const float* __restrict__ bf,
                                                   const float* __restrict__ bs) {
    __shared__ float Xs[32 * 129];
    __shared__ float Wsm[32 * 128];
    if (blockIdx.x < 2 * PB) {
        proj_body(Xs, Wsm, blockIdx.x, wf, ws, bf, bs);
    } else {
        int e = (blockIdx.x - 2 * PB) * 256 + threadIdx.x;
        scatter_feat_body(e, ei, ea, sw, sb);
    }
}

// Standalone proj for conv #2
__global__ __launch_bounds__(256) void k_proj(const float* __restrict__ wf,
                                              const float* __restrict__ ws,
                                              const float* __restrict__ bf,
                                              const float* __restrict__ bs) {
    __shared__ float Xs[32 * 129];
    __shared__ float Wsm[32 * 128];
    proj_body(Xs, Wsm, blockIdx.x, wf, ws, bf, bs);
}

// ---------------------------------------------------------------------------
// K_edge_csr: one WARP per dst node; lane l owns channels 2l,2l+1 as half2.
// Per edge: 2 broadcast LDG.128 (E tile incl. src id) + 1 LDG.64 gather.
// Unroll 4; fused residual + relu epilogue.
// ---------------------------------------------------------------------------
__global__ __launch_bounds__(256) void k_edge_csr(const float* __restrict__ wef,
                                                  const float* __restrict__ wes,
                                                  float* __restrict__ out,
                                                  int final_) {
    int gw = (blockIdx.x * 256 + threadIdx.x) >> 5;
    int l = threadIdx.x & 31;
    if (gw >= NN) return;
    const int n = gw;

    __half2 wf2[5], ws2[5];
#pragma unroll
    for (int k = 0; k < 5; k++) {
        wf2[k] = __floats2half2_rn(wef[k * 64 + 2 * l], wef[k * 64 + 2 * l + 1]);
        ws2[k] = __floats2half2_rn(wes[k * 64 + 2 * l], wes[k * 64 + 2 * l + 1]);
    }
    const __half2 cHalf = __float2half2_rn(0.5f);

    uint2 dw = g_Dpk[(size_t)n * 32 + l];
    const __half2 Df2 = u2h(dw.x);
    const __half2 Ds2 = u2h(dw.y);

    float m0 = 0.0f, m1 = 0.0f;
    const int beg = __ldg(&g_off[n]), end = __ldg(&g_off[n + 1]);

#pragma unroll 4
    for (int k = beg; k < end; k++) {
        uint4 ewa = *reinterpret_cast<const uint4*>(&g_E32[(size_t)k * 8]);
        uint4 ewb = *reinterpret_cast<const uint4*>(&g_E32[(size_t)k * 8 + 4]);
        int s = (int)ewb.y;                                   // src id
        uint2 sp_ = __ldg(&g_Spk[(size_t)s * 32 + l]);        // 8B gather

        __half2 zf = __hadd2(Df2, u2h(sp_.x));
        zf = __hfma2(u2h(ewa.x), wf2[0], zf);
        zf = __hfma2(u2h(ewa.y), wf2[1], zf);
        zf = __hfma2(u2h(ewa.z), wf2[2], zf);
        zf = __hfma2(u2h(ewa.w), wf2[3], zf);
        zf = __hfma2(u2h(ewb.x), wf2[4], zf);

        __half2 zs = __hadd2(Ds2, u2h(sp_.y));
        zs = __hfma2(u2h(ewa.x), ws2[0], zs);
        zs = __hfma2(u2h(ewa.y), ws2[1], zs);
        zs = __hfma2(u2h(ewa.z), ws2[2], zs);
        zs = __hfma2(u2h(ewa.w), ws2[3], zs);
        zs = __hfma2(u2h(ewb.x), ws2[4], zs);

        __half2 g2 = __hfma2(tanh_h2(__hmul2(zf, cHalf)), cHalf, cHalf);
        float2 gf = __half22float2(g2);
        float2 zsf = __half22float2(zs);

        m0 = fmaf(gf.x, softplus_f(zsf.x), m0);
        m1 = fmaf(gf.y, softplus_f(zsf.y), m1);
    }

    float2 x = *reinterpret_cast<const float2*>(g_X + (size_t)n * 64 + 2 * l);
    float2 r = make_float2(fmaxf(x.x + m0, 0.0f), fmaxf(x.y + m1, 0.0f));
    if (final_) {
        *reinterpret_cast<float2*>(out + (size_t)n * 64 + 2 * l) = r;
    } else {
        *reinterpret_cast<float2*>(g_X + (size_t)n * 64 + 2 * l) = r;
    }
}

// ---------------------------------------------------------------------------
// Launch. Inputs: h, edge_index, edge_weight, edge_attr, data,
// lin0_w, lin0_b, short_w, short_b, conv_f_w, conv_f_b, conv_s_w, conv_s_b
// Single stream, 6 launches. Launch 6 = edge conv #2 (ncu -s 5 -c 1 target).
// ---------------------------------------------------------------------------
extern "C" void kernel_launch(void* const* d_in, const int* in_sizes, int n_in,
                              void* d_out, int out_size) {
    int o = (n_in >= 13) ? 0 : -1;

    const float* h = (const float*)d_in[0];
    const int* ei = (const int*)d_in[1];  // int32 [2, NE]
    const float* ea = (const float*)d_in[3];
    const float* lin0_w = (const float*)d_in[5 + o];
    const float* lin0_b = (const float*)d_in[6 + o];
    const float* short_w = (const float*)d_in[7 + o];
    const float* short_b = (const float*)d_in[8 + o];
    const float* cfw = (const float*)d_in[9 + o];   // [2,133,64]
    const float* cfb = (const float*)d_in[10 + o];  // [2,64]
    const float* csw = (const float*)d_in[11 + o];
    const float* csb = (const float*)d_in[12 + o];
    float* out = (float*)d_out;

    // 1: histogram (edges) + lin0 GEMM (nodes), fused, independent
    k_hist_lin0<<<EB + LB, 256>>>(ei, h, lin0_w, lin0_b);
    // 2: offsets
    k_scan<<<1, 1024>>>();
    // 3: proj conv#1 + scatter_feat, fused, independent
    k_scat_proj<<<2 * PB + EB, 256>>>(ei, ea, short_w, short_b,
                                      cfw, csw, cfb, csb);
    // 4: edge conv #1
    k_edge_csr<<<(NN * 32 + 255) / 256, 256>>>(cfw + 128 * 64, csw + 128 * 64,
                                               out, 0);
    // 5: proj conv #2
    k_proj<<<2 * PB, 256>>>(cfw + (size_t)133 * 64, csw + (size_t)133 * 64,
                            cfb + 64, csb + 64);
    // 6: edge conv #2
    k_edge_csr<<<(NN * 32 + 255) / 256, 256>>>(
        cfw + (size_t)133 * 64 + 128 * 64, csw + (size_t)133 * 64 + 128 * 64,
        out, 1);
}